// round 6
// baseline (speedup 1.0000x reference)
#include <cuda_runtime.h>
#include <math.h>
#include <stdint.h>

// Problem constants
#define Bdim   2
#define Sdim   2048
#define Edim   2048
#define Hdim   16
#define HKVdim 4
#define Ddim   128
#define KQVdim 2048
#define KVdim  512            // HKV * D — compact Q / attn-out width
#define WIN    256
#define Mrows  (Bdim * Sdim)  // 4096

// Scratch (static __device__ — no allocation allowed)
__device__ float g_q [(size_t)Mrows * KVdim];
__device__ float g_k [(size_t)Mrows * KVdim];
__device__ float g_v [(size_t)Mrows * KVdim];
__device__ float g_ao[(size_t)Mrows * KVdim];
__device__ float g_wf[(size_t)Edim  * KVdim];    // folded Wo

// ---------------------------------------------------------------------------
// 3xTF32 tensor-core GEMM (fp32-accurate): Y = X @ W^T (+bias)
// BM=128, BN=128, BK=16, 256 threads (8 warps 2x4), 64x32 per warp.
// smem holds PRE-SPLIT (hi,lo) tf32 pairs as uint2 — split once at staging,
// mainloop is pure LDS.64 + MMA.
// ---------------------------------------------------------------------------
#define BM 128
#define BN 128
#define BK 16
#define MSTR (BM + 4)             // 132 uint2 stride
#define TILE_U2 (BK * MSTR)       // uint2 per matrix per stage
#define SMEM_BYTES (4 * TILE_U2 * 8)   // 2 stages x (A,B) = 67584 B

__device__ __forceinline__ uint32_t f2tf32(float f) {
    uint32_t r;
    asm("cvt.rna.tf32.f32 %0, %1;" : "=r"(r) : "f"(f));
    return r;
}

__device__ __forceinline__ uint2 split_tf32(float f) {
    uint2 r;
    r.x = f2tf32(f);
    r.y = f2tf32(f - __uint_as_float(r.x));
    return r;
}

__device__ __forceinline__ void mma_tf32(float c[4], uint32_t a0, uint32_t a1,
                                         uint32_t a2, uint32_t a3,
                                         uint32_t b0, uint32_t b1) {
    asm volatile(
        "mma.sync.aligned.m16n8k8.row.col.f32.tf32.tf32.f32 "
        "{%0,%1,%2,%3}, {%4,%5,%6,%7}, {%8,%9}, {%0,%1,%2,%3};"
        : "+f"(c[0]), "+f"(c[1]), "+f"(c[2]), "+f"(c[3])
        : "r"(a0), "r"(a1), "r"(a2), "r"(a3), "r"(b0), "r"(b1));
}

// Batched variant: gridDim.z selects (W, Y) pair. K fixed per launch.
__global__ void __launch_bounds__(256)
gemm_3xtf32(const float* __restrict__ X,
            const float* __restrict__ W0, const float* __restrict__ W1,
            const float* __restrict__ W2,
            float* __restrict__ Y0, float* __restrict__ Y1,
            float* __restrict__ Y2,
            const float* __restrict__ bias,
            int N, int K)
{
    extern __shared__ uint2 sm[];
    uint2* As = sm;                  // [2][BK][MSTR]
    uint2* Bs = sm + 2 * TILE_U2;

    const float* W = (blockIdx.z == 0) ? W0 : (blockIdx.z == 1) ? W1 : W2;
    float*       Y = (blockIdx.z == 0) ? Y0 : (blockIdx.z == 1) ? Y1 : Y2;

    const int tid  = threadIdx.x;
    const int warp = tid >> 5;
    const int lane = tid & 31;
    const int g    = lane >> 2;
    const int tg   = lane & 3;
    const int wm   = warp & 1;
    const int wn   = warp >> 1;
    const int bm   = blockIdx.y * BM;
    const int bn   = blockIdx.x * BN;

    const int ldrow0 = tid >> 2;     // rows 0..63 (p=0), +64 (p=1)
    const int ldkv   = tid & 3;

    float acc[4][4][4];
    #pragma unroll
    for (int i = 0; i < 4; i++)
        #pragma unroll
        for (int j = 0; j < 4; j++)
            #pragma unroll
            for (int c = 0; c < 4; c++) acc[i][j][c] = 0.0f;

    const int T = K / BK;

    // Prologue: tile 0 -> stage 0
    #pragma unroll
    for (int p = 0; p < 2; p++) {
        int row = ldrow0 + p * 64;
        float4 a = *reinterpret_cast<const float4*>(&X[(size_t)(bm + row) * K + ldkv * 4]);
        As[(ldkv*4+0)*MSTR + row] = split_tf32(a.x);
        As[(ldkv*4+1)*MSTR + row] = split_tf32(a.y);
        As[(ldkv*4+2)*MSTR + row] = split_tf32(a.z);
        As[(ldkv*4+3)*MSTR + row] = split_tf32(a.w);
        float4 b = *reinterpret_cast<const float4*>(&W[(size_t)(bn + row) * K + ldkv * 4]);
        Bs[(ldkv*4+0)*MSTR + row] = split_tf32(b.x);
        Bs[(ldkv*4+1)*MSTR + row] = split_tf32(b.y);
        Bs[(ldkv*4+2)*MSTR + row] = split_tf32(b.z);
        Bs[(ldkv*4+3)*MSTR + row] = split_tf32(b.w);
    }
    __syncthreads();

    for (int t = 0; t < T; t++) {
        const int cur = (t & 1) * TILE_U2;
        const int nxt = ((t + 1) & 1) * TILE_U2;

        // Prefetch next tile into registers (overlaps with MMA)
        float4 pa[2], pb[2];
        if (t + 1 < T) {
            const int k0 = (t + 1) * BK;
            #pragma unroll
            for (int p = 0; p < 2; p++) {
                int row = ldrow0 + p * 64;
                pa[p] = *reinterpret_cast<const float4*>(&X[(size_t)(bm + row) * K + k0 + ldkv * 4]);
                pb[p] = *reinterpret_cast<const float4*>(&W[(size_t)(bn + row) * K + k0 + ldkv * 4]);
            }
        }

        // Compute: 2 k-steps of 8; fragments carry (hi,lo) in one LDS.64
        #pragma unroll
        for (int ks = 0; ks < BK; ks += 8) {
            uint2 a[4][4], b[4][2];
            #pragma unroll
            for (int i = 0; i < 4; i++) {
                int row = wm * 64 + i * 16 + g;
                a[i][0] = As[cur + (ks + tg    )*MSTR + row];
                a[i][1] = As[cur + (ks + tg    )*MSTR + row + 8];
                a[i][2] = As[cur + (ks + tg + 4)*MSTR + row];
                a[i][3] = As[cur + (ks + tg + 4)*MSTR + row + 8];
            }
            #pragma unroll
            for (int j = 0; j < 4; j++) {
                int col = wn * 32 + j * 8 + g;
                b[j][0] = Bs[cur + (ks + tg    )*MSTR + col];
                b[j][1] = Bs[cur + (ks + tg + 4)*MSTR + col];
            }
            #pragma unroll
            for (int i = 0; i < 4; i++)
                #pragma unroll
                for (int j = 0; j < 4; j++) {
                    mma_tf32(acc[i][j], a[i][0].y, a[i][1].y, a[i][2].y, a[i][3].y,
                             b[j][0].x, b[j][1].x);
                    mma_tf32(acc[i][j], a[i][0].x, a[i][1].x, a[i][2].x, a[i][3].x,
                             b[j][0].y, b[j][1].y);
                    mma_tf32(acc[i][j], a[i][0].x, a[i][1].x, a[i][2].x, a[i][3].x,
                             b[j][0].x, b[j][1].x);
                }
        }

        // Stage next tile (register -> split -> smem); one sync per iter
        if (t + 1 < T) {
            #pragma unroll
            for (int p = 0; p < 2; p++) {
                int row = ldrow0 + p * 64;
                As[nxt + (ldkv*4+0)*MSTR + row] = split_tf32(pa[p].x);
                As[nxt + (ldkv*4+1)*MSTR + row] = split_tf32(pa[p].y);
                As[nxt + (ldkv*4+2)*MSTR + row] = split_tf32(pa[p].z);
                As[nxt + (ldkv*4+3)*MSTR + row] = split_tf32(pa[p].w);
                Bs[nxt + (ldkv*4+0)*MSTR + row] = split_tf32(pb[p].x);
                Bs[nxt + (ldkv*4+1)*MSTR + row] = split_tf32(pb[p].y);
                Bs[nxt + (ldkv*4+2)*MSTR + row] = split_tf32(pb[p].z);
                Bs[nxt + (ldkv*4+3)*MSTR + row] = split_tf32(pb[p].w);
            }
            __syncthreads();
        }
    }

    // Epilogue
    #pragma unroll
    for (int i = 0; i < 4; i++) {
        #pragma unroll
        for (int j = 0; j < 4; j++) {
            int row = bm + wm * 64 + i * 16 + g;
            int col = bn + wn * 32 + j * 8 + 2 * tg;
            float b0 = bias ? bias[col]     : 0.0f;
            float b1 = bias ? bias[col + 1] : 0.0f;
            float2 v0 = make_float2(acc[i][j][0] + b0, acc[i][j][1] + b1);
            float2 v1 = make_float2(acc[i][j][2] + b0, acc[i][j][3] + b1);
            *reinterpret_cast<float2*>(&Y[(size_t)row * N + col])       = v0;
            *reinterpret_cast<float2*>(&Y[(size_t)(row + 8) * N + col]) = v1;
        }
    }
}

// ---------------------------------------------------------------------------
// Fold Wo: Wf[e, g*D+d] = sum_{u=0..3} Wo[e, (4g+u)*D + d]
// ---------------------------------------------------------------------------
__global__ void fold_wo(const float* __restrict__ Wo, float* __restrict__ Wf)
{
    int i = blockIdx.x * blockDim.x + threadIdx.x;
    if (i >= Edim * KVdim) return;
    int e = i / KVdim;
    int c = i % KVdim;
    int gh = c / Ddim, d = c % Ddim;
    float s = 0.0f;
    #pragma unroll
    for (int u = 0; u < 4; u++)
        s += Wo[(size_t)e * KQVdim + (size_t)(gh * 4 + u) * Ddim + d];
    Wf[i] = s;
}

// ---------------------------------------------------------------------------
// Sliding-window GQA attention (flash-style), 4 distinct kv heads.
// ---------------------------------------------------------------------------
__global__ void __launch_bounds__(256, 2)
attn_window(const float* __restrict__ q, const float* __restrict__ k,
            const float* __restrict__ v, float* __restrict__ out)
{
    __shared__ float Qs[32][Ddim];
    __shared__ float Ks[Ddim][33];
    __shared__ float Vs[32][Ddim];

    const int tid  = threadIdx.x;
    const int warp = tid >> 5;
    const int lane = tid & 31;

    const int bh  = blockIdx.y;
    const int b   = bh / HKVdim;
    const int kvh = bh % HKVdim;
    const int q0  = blockIdx.x * 32;

    const float* qptr = q + ((size_t)b * Sdim + q0) * KVdim + kvh * Ddim;

    #pragma unroll
    for (int e = 0; e < 16; e++) {
        int lin = e * 256 + tid;
        int r = lin >> 7, d = lin & 127;
        Qs[r][d] = qptr[(size_t)r * KVdim + d];
    }

    float m[4], l[4], O[4][4];
    #pragma unroll
    for (int r = 0; r < 4; r++) {
        m[r] = -1e30f; l[r] = 0.0f;
        #pragma unroll
        for (int c = 0; c < 4; c++) O[r][c] = 0.0f;
    }

    int ktlo = q0 - (WIN - 1);
    if (ktlo < 0) ktlo = 0;
    ktlo = (ktlo / 32) * 32;

    for (int k0 = ktlo; k0 <= q0; k0 += 32) {
        const float* kptr = k + ((size_t)b * Sdim + k0) * KVdim + kvh * Ddim;
        const float* vptr = v + ((size_t)b * Sdim + k0) * KVdim + kvh * Ddim;
        __syncthreads();
        #pragma unroll
        for (int e = 0; e < 16; e++) {
            int lin = e * 256 + tid;
            int j = lin >> 7, d = lin & 127;
            Ks[d][j] = kptr[(size_t)j * KVdim + d];
            Vs[j][d] = vptr[(size_t)j * KVdim + d];
        }
        __syncthreads();

        #pragma unroll
        for (int r = 0; r < 4; r++) {
            const int row = warp * 4 + r;
            const int i   = q0 + row;
            const int jg  = k0 + lane;

            float s = 0.0f;
            #pragma unroll
            for (int d = 0; d < Ddim; d++)
                s = fmaf(Qs[row][d], Ks[d][lane], s);

            const bool valid = (jg <= i) && (jg > i - WIN);
            s = valid ? s : -1e30f;

            float mt = s;
            #pragma unroll
            for (int off = 16; off; off >>= 1)
                mt = fmaxf(mt, __shfl_xor_sync(0xffffffffu, mt, off));
            const float mnew  = fmaxf(m[r], mt);
            const float p     = valid ? __expf(s - mnew) : 0.0f;
            const float alpha = __expf(m[r] - mnew);
            m[r] = mnew;

            float rs = p;
            #pragma unroll
            for (int off = 16; off; off >>= 1)
                rs += __shfl_xor_sync(0xffffffffu, rs, off);
            l[r] = l[r] * alpha + rs;

            #pragma unroll
            for (int c = 0; c < 4; c++) O[r][c] *= alpha;
            #pragma unroll
            for (int j = 0; j < 32; j++) {
                const float pj = __shfl_sync(0xffffffffu, p, j);
                #pragma unroll
                for (int c = 0; c < 4; c++)
                    O[r][c] = fmaf(pj, Vs[j][c * 32 + lane], O[r][c]);
            }
        }
    }

    float* optr = out + ((size_t)b * Sdim + q0) * KVdim + kvh * Ddim;
    #pragma unroll
    for (int r = 0; r < 4; r++) {
        const int row = warp * 4 + r;
        const float inv = 1.0f / l[r];
        #pragma unroll
        for (int c = 0; c < 4; c++)
            optr[(size_t)row * KVdim + c * 32 + lane] = O[r][c] * inv;
    }
}

// ---------------------------------------------------------------------------
// Launch
// ---------------------------------------------------------------------------
extern "C" void kernel_launch(void* const* d_in, const int* in_sizes, int n_in,
                              void* d_out, int out_size)
{
    const float* x  = (const float*)d_in[0];
    const float* Wq = (const float*)d_in[1];   // only rows 0..511 used
    const float* Wk = (const float*)d_in[2];
    const float* Wv = (const float*)d_in[3];
    const float* Wo = (const float*)d_in[4];
    const float* bo = (const float*)d_in[5];
    float* out = (float*)d_out;

    float *qb, *kb, *vb, *ab, *wf;
    cudaGetSymbolAddress((void**)&qb, g_q);
    cudaGetSymbolAddress((void**)&kb, g_k);
    cudaGetSymbolAddress((void**)&vb, g_v);
    cudaGetSymbolAddress((void**)&ab, g_ao);
    cudaGetSymbolAddress((void**)&wf, g_wf);

    static bool attr_set = false;
    if (!attr_set) {
        cudaFuncSetAttribute(gemm_3xtf32,
                             cudaFuncAttributeMaxDynamicSharedMemorySize,
                             SMEM_BYTES);
        attr_set = true;
    }

    fold_wo<<<(Edim * KVdim + 255) / 256, 256>>>(Wo, wf);

    // Batched QKV projections (z selects weight/output)
    gemm_3xtf32<<<dim3(KVdim / BN, Mrows / BM, 3), 256, SMEM_BYTES>>>(
        x, Wq, Wk, Wv, qb, kb, vb, nullptr, KVdim, Edim);

    attn_window<<<dim3(Sdim / 32, Bdim * HKVdim), 256>>>(qb, kb, vb, ab);

    // Output projection with folded Wo + bias
    gemm_3xtf32<<<dim3(Edim / BN, Mrows / BM, 1), 256, SMEM_BYTES>>>(
        ab, wf, wf, wf, out, out, out, bo, Edim, KVdim);
}

// round 8
// speedup vs baseline: 1.1810x; 1.1810x over previous
#include <cuda_runtime.h>
#include <math.h>
#include <stdint.h>

// Problem constants
#define Bdim   2
#define Sdim   2048
#define Edim   2048
#define Hdim   16
#define HKVdim 4
#define Ddim   128
#define KQVdim 2048
#define KVdim  512            // HKV * D — compact Q / attn-out width
#define WIN    256
#define Mrows  (Bdim * Sdim)  // 4096

// Scratch (static __device__ — no allocation allowed)
__device__ float g_q [(size_t)Mrows * KVdim];
__device__ float g_k [(size_t)Mrows * KVdim];
__device__ float g_v [(size_t)Mrows * KVdim];
__device__ float g_ao[(size_t)Mrows * KVdim];
__device__ float g_wf[(size_t)Edim  * KVdim];    // folded Wo

// ---------------------------------------------------------------------------
// 3xTF32 tensor-core GEMM (fp32-accurate): Y = X @ W^T (+bias)
// BM=128, BN=128, BK=16, 256 threads (8 warps 2x4), 64x32 per warp.
// smem: FOUR u32 planes per stage (Ahi, Alo, Bhi, Blo) — split once at
// staging; mainloop is pure LDS.32 + MMA with R4-proven conflict-free
// addressing (plane stride 2112 words == 0 mod 32 banks, so every plane
// shares the validated pattern).
// ---------------------------------------------------------------------------
#define BM 128
#define BN 128
#define BK 16
#define MSTR  132                  // u32 stride per k-row
#define PLANE (BK * MSTR)          // 2112 u32 per plane
#define STAGE (4 * PLANE)          // Ahi,Alo,Bhi,Blo
#define SMEM_BYTES (2 * STAGE * 4) // 67584 B

__device__ __forceinline__ uint32_t f2tf32(float f) {
    uint32_t r;
    asm("cvt.rna.tf32.f32 %0, %1;" : "=r"(r) : "f"(f));
    return r;
}

__device__ __forceinline__ void mma_tf32(float c[4], uint32_t a0, uint32_t a1,
                                         uint32_t a2, uint32_t a3,
                                         uint32_t b0, uint32_t b1) {
    asm volatile(
        "mma.sync.aligned.m16n8k8.row.col.f32.tf32.tf32.f32 "
        "{%0,%1,%2,%3}, {%4,%5,%6,%7}, {%8,%9}, {%0,%1,%2,%3};"
        : "+f"(c[0]), "+f"(c[1]), "+f"(c[2]), "+f"(c[3])
        : "r"(a0), "r"(a1), "r"(a2), "r"(a3), "r"(b0), "r"(b1));
}

// Store one fp32 value split into (hi, lo) tf32 planes.
__device__ __forceinline__ void stage_split(uint32_t* hi, uint32_t* lo,
                                            int idx, float f) {
    uint32_t h = f2tf32(f);
    hi[idx] = h;
    lo[idx] = f2tf32(f - __uint_as_float(h));
}

// Batched: gridDim.z selects (W, Y) pair. K fixed per launch.
__global__ void __launch_bounds__(256)
gemm_3xtf32(const float* __restrict__ X,
            const float* __restrict__ W0, const float* __restrict__ W1,
            const float* __restrict__ W2,
            float* __restrict__ Y0, float* __restrict__ Y1,
            float* __restrict__ Y2,
            const float* __restrict__ bias,
            int N, int K)
{
    extern __shared__ uint32_t sm[];

    const float* W = (blockIdx.z == 0) ? W0 : (blockIdx.z == 1) ? W1 : W2;
    float*       Y = (blockIdx.z == 0) ? Y0 : (blockIdx.z == 1) ? Y1 : Y2;

    const int tid  = threadIdx.x;
    const int warp = tid >> 5;
    const int lane = tid & 31;
    const int g    = lane >> 2;
    const int tg   = lane & 3;
    const int wm   = warp & 1;
    const int wn   = warp >> 1;
    const int bm   = blockIdx.y * BM;
    const int bn   = blockIdx.x * BN;

    const int ldrow0 = tid >> 2;     // rows 0..63 (p=0), +64 (p=1)
    const int ldkv   = tid & 3;

    float acc[4][4][4];
    #pragma unroll
    for (int i = 0; i < 4; i++)
        #pragma unroll
        for (int j = 0; j < 4; j++)
            #pragma unroll
            for (int c = 0; c < 4; c++) acc[i][j][c] = 0.0f;

    const int T = K / BK;

    // Prologue: tile 0 -> stage 0
    {
        uint32_t* Ahi = sm;
        uint32_t* Alo = sm + PLANE;
        uint32_t* Bhi = sm + 2 * PLANE;
        uint32_t* Blo = sm + 3 * PLANE;
        #pragma unroll
        for (int p = 0; p < 2; p++) {
            int row = ldrow0 + p * 64;
            float4 a = *reinterpret_cast<const float4*>(&X[(size_t)(bm + row) * K + ldkv * 4]);
            stage_split(Ahi, Alo, (ldkv*4+0)*MSTR + row, a.x);
            stage_split(Ahi, Alo, (ldkv*4+1)*MSTR + row, a.y);
            stage_split(Ahi, Alo, (ldkv*4+2)*MSTR + row, a.z);
            stage_split(Ahi, Alo, (ldkv*4+3)*MSTR + row, a.w);
            float4 b = *reinterpret_cast<const float4*>(&W[(size_t)(bn + row) * K + ldkv * 4]);
            stage_split(Bhi, Blo, (ldkv*4+0)*MSTR + row, b.x);
            stage_split(Bhi, Blo, (ldkv*4+1)*MSTR + row, b.y);
            stage_split(Bhi, Blo, (ldkv*4+2)*MSTR + row, b.z);
            stage_split(Bhi, Blo, (ldkv*4+3)*MSTR + row, b.w);
        }
    }
    __syncthreads();

    for (int t = 0; t < T; t++) {
        const uint32_t* Ahi = sm + (t & 1) * STAGE;
        const uint32_t* Alo = Ahi + PLANE;
        const uint32_t* Bhi = Ahi + 2 * PLANE;
        const uint32_t* Blo = Ahi + 3 * PLANE;

        // Prefetch next tile into registers (overlaps with MMA)
        float4 pa[2], pb[2];
        if (t + 1 < T) {
            const int k0 = (t + 1) * BK;
            #pragma unroll
            for (int p = 0; p < 2; p++) {
                int row = ldrow0 + p * 64;
                pa[p] = *reinterpret_cast<const float4*>(&X[(size_t)(bm + row) * K + k0 + ldkv * 4]);
                pb[p] = *reinterpret_cast<const float4*>(&W[(size_t)(bn + row) * K + k0 + ldkv * 4]);
            }
        }

        // Compute: 2 k-steps of 8; pure LDS + MMA
        #pragma unroll
        for (int ks = 0; ks < BK; ks += 8) {
            uint32_t ah[4][4], al[4][4], bh[4][2], bl[4][2];
            #pragma unroll
            for (int i = 0; i < 4; i++) {
                int row = wm * 64 + i * 16 + g;
                int i0 = (ks + tg    ) * MSTR + row;
                int i1 = (ks + tg + 4) * MSTR + row;
                ah[i][0] = Ahi[i0];     al[i][0] = Alo[i0];
                ah[i][1] = Ahi[i0 + 8]; al[i][1] = Alo[i0 + 8];
                ah[i][2] = Ahi[i1];     al[i][2] = Alo[i1];
                ah[i][3] = Ahi[i1 + 8]; al[i][3] = Alo[i1 + 8];
            }
            #pragma unroll
            for (int j = 0; j < 4; j++) {
                int col = wn * 32 + j * 8 + g;
                int i0 = (ks + tg    ) * MSTR + col;
                int i1 = (ks + tg + 4) * MSTR + col;
                bh[j][0] = Bhi[i0]; bl[j][0] = Blo[i0];
                bh[j][1] = Bhi[i1]; bl[j][1] = Blo[i1];
            }
            #pragma unroll
            for (int i = 0; i < 4; i++)
                #pragma unroll
                for (int j = 0; j < 4; j++) {
                    mma_tf32(acc[i][j], al[i][0], al[i][1], al[i][2], al[i][3],
                             bh[j][0], bh[j][1]);
                    mma_tf32(acc[i][j], ah[i][0], ah[i][1], ah[i][2], ah[i][3],
                             bl[j][0], bl[j][1]);
                    mma_tf32(acc[i][j], ah[i][0], ah[i][1], ah[i][2], ah[i][3],
                             bh[j][0], bh[j][1]);
                }
        }

        // Stage next tile; one sync per iter
        if (t + 1 < T) {
            uint32_t* nAhi = sm + ((t + 1) & 1) * STAGE;
            uint32_t* nAlo = nAhi + PLANE;
            uint32_t* nBhi = nAhi + 2 * PLANE;
            uint32_t* nBlo = nAhi + 3 * PLANE;
            #pragma unroll
            for (int p = 0; p < 2; p++) {
                int row = ldrow0 + p * 64;
                stage_split(nAhi, nAlo, (ldkv*4+0)*MSTR + row, pa[p].x);
                stage_split(nAhi, nAlo, (ldkv*4+1)*MSTR + row, pa[p].y);
                stage_split(nAhi, nAlo, (ldkv*4+2)*MSTR + row, pa[p].z);
                stage_split(nAhi, nAlo, (ldkv*4+3)*MSTR + row, pa[p].w);
                stage_split(nBhi, nBlo, (ldkv*4+0)*MSTR + row, pb[p].x);
                stage_split(nBhi, nBlo, (ldkv*4+1)*MSTR + row, pb[p].y);
                stage_split(nBhi, nBlo, (ldkv*4+2)*MSTR + row, pb[p].z);
                stage_split(nBhi, nBlo, (ldkv*4+3)*MSTR + row, pb[p].w);
            }
            __syncthreads();
        }
    }

    // Epilogue
    #pragma unroll
    for (int i = 0; i < 4; i++) {
        #pragma unroll
        for (int j = 0; j < 4; j++) {
            int row = bm + wm * 64 + i * 16 + g;
            int col = bn + wn * 32 + j * 8 + 2 * tg;
            float b0 = bias ? bias[col]     : 0.0f;
            float b1 = bias ? bias[col + 1] : 0.0f;
            float2 v0 = make_float2(acc[i][j][0] + b0, acc[i][j][1] + b1);
            float2 v1 = make_float2(acc[i][j][2] + b0, acc[i][j][3] + b1);
            *reinterpret_cast<float2*>(&Y[(size_t)row * N + col])       = v0;
            *reinterpret_cast<float2*>(&Y[(size_t)(row + 8) * N + col]) = v1;
        }
    }
}

// ---------------------------------------------------------------------------
// Fold Wo: Wf[e, g*D+d] = sum_{u=0..3} Wo[e, (4g+u)*D + d]
// ---------------------------------------------------------------------------
__global__ void fold_wo(const float* __restrict__ Wo, float* __restrict__ Wf)
{
    int i = blockIdx.x * blockDim.x + threadIdx.x;
    if (i >= Edim * KVdim) return;
    int e = i / KVdim;
    int c = i % KVdim;
    int gh = c / Ddim, d = c % Ddim;
    float s = 0.0f;
    #pragma unroll
    for (int u = 0; u < 4; u++)
        s += Wo[(size_t)e * KQVdim + (size_t)(gh * 4 + u) * Ddim + d];
    Wf[i] = s;
}

// ---------------------------------------------------------------------------
// Sliding-window GQA attention (flash-style), 4 distinct kv heads.
// ---------------------------------------------------------------------------
__global__ void __launch_bounds__(256, 2)
attn_window(const float* __restrict__ q, const float* __restrict__ k,
            const float* __restrict__ v, float* __restrict__ out)
{
    __shared__ float Qs[32][Ddim];
    __shared__ float Ks[Ddim][33];
    __shared__ float Vs[32][Ddim];

    const int tid  = threadIdx.x;
    const int warp = tid >> 5;
    const int lane = tid & 31;

    const int bh  = blockIdx.y;
    const int b   = bh / HKVdim;
    const int kvh = bh % HKVdim;
    const int q0  = blockIdx.x * 32;

    const float* qptr = q + ((size_t)b * Sdim + q0) * KVdim + kvh * Ddim;

    #pragma unroll
    for (int e = 0; e < 16; e++) {
        int lin = e * 256 + tid;
        int r = lin >> 7, d = lin & 127;
        Qs[r][d] = qptr[(size_t)r * KVdim + d];
    }

    float m[4], l[4], O[4][4];
    #pragma unroll
    for (int r = 0; r < 4; r++) {
        m[r] = -1e30f; l[r] = 0.0f;
        #pragma unroll
        for (int c = 0; c < 4; c++) O[r][c] = 0.0f;
    }

    int ktlo = q0 - (WIN - 1);
    if (ktlo < 0) ktlo = 0;
    ktlo = (ktlo / 32) * 32;

    for (int k0 = ktlo; k0 <= q0; k0 += 32) {
        const float* kptr = k + ((size_t)b * Sdim + k0) * KVdim + kvh * Ddim;
        const float* vptr = v + ((size_t)b * Sdim + k0) * KVdim + kvh * Ddim;
        __syncthreads();
        #pragma unroll
        for (int e = 0; e < 16; e++) {
            int lin = e * 256 + tid;
            int j = lin >> 7, d = lin & 127;
            Ks[d][j] = kptr[(size_t)j * KVdim + d];
            Vs[j][d] = vptr[(size_t)j * KVdim + d];
        }
        __syncthreads();

        #pragma unroll
        for (int r = 0; r < 4; r++) {
            const int row = warp * 4 + r;
            const int i   = q0 + row;
            const int jg  = k0 + lane;

            float s = 0.0f;
            #pragma unroll
            for (int d = 0; d < Ddim; d++)
                s = fmaf(Qs[row][d], Ks[d][lane], s);

            const bool valid = (jg <= i) && (jg > i - WIN);
            s = valid ? s : -1e30f;

            float mt = s;
            #pragma unroll
            for (int off = 16; off; off >>= 1)
                mt = fmaxf(mt, __shfl_xor_sync(0xffffffffu, mt, off));
            const float mnew  = fmaxf(m[r], mt);
            const float p     = valid ? __expf(s - mnew) : 0.0f;
            const float alpha = __expf(m[r] - mnew);
            m[r] = mnew;

            float rs = p;
            #pragma unroll
            for (int off = 16; off; off >>= 1)
                rs += __shfl_xor_sync(0xffffffffu, rs, off);
            l[r] = l[r] * alpha + rs;

            #pragma unroll
            for (int c = 0; c < 4; c++) O[r][c] *= alpha;
            #pragma unroll
            for (int j = 0; j < 32; j++) {
                const float pj = __shfl_sync(0xffffffffu, p, j);
                #pragma unroll
                for (int c = 0; c < 4; c++)
                    O[r][c] = fmaf(pj, Vs[j][c * 32 + lane], O[r][c]);
            }
        }
    }

    float* optr = out + ((size_t)b * Sdim + q0) * KVdim + kvh * Ddim;
    #pragma unroll
    for (int r = 0; r < 4; r++) {
        const int row = warp * 4 + r;
        const float inv = 1.0f / l[r];
        #pragma unroll
        for (int c = 0; c < 4; c++)
            optr[(size_t)row * KVdim + c * 32 + lane] = O[r][c] * inv;
    }
}

// ---------------------------------------------------------------------------
// Launch
// ---------------------------------------------------------------------------
extern "C" void kernel_launch(void* const* d_in, const int* in_sizes, int n_in,
                              void* d_out, int out_size)
{
    const float* x  = (const float*)d_in[0];
    const float* Wq = (const float*)d_in[1];   // only rows 0..511 used
    const float* Wk = (const float*)d_in[2];
    const float* Wv = (const float*)d_in[3];
    const float* Wo = (const float*)d_in[4];
    const float* bo = (const float*)d_in[5];
    float* out = (float*)d_out;

    float *qb, *kb, *vb, *ab, *wf;
    cudaGetSymbolAddress((void**)&qb, g_q);
    cudaGetSymbolAddress((void**)&kb, g_k);
    cudaGetSymbolAddress((void**)&vb, g_v);
    cudaGetSymbolAddress((void**)&ab, g_ao);
    cudaGetSymbolAddress((void**)&wf, g_wf);

    static bool attr_set = false;
    if (!attr_set) {
        cudaFuncSetAttribute(gemm_3xtf32,
                             cudaFuncAttributeMaxDynamicSharedMemorySize,
                             SMEM_BYTES);
        attr_set = true;
    }

    fold_wo<<<(Edim * KVdim + 255) / 256, 256>>>(Wo, wf);

    // Batched QKV projections (z selects weight/output)
    gemm_3xtf32<<<dim3(KVdim / BN, Mrows / BM, 3), 256, SMEM_BYTES>>>(
        x, Wq, Wk, Wv, qb, kb, vb, nullptr, KVdim, Edim);

    attn_window<<<dim3(Sdim / 32, Bdim * HKVdim), 256>>>(qb, kb, vb, ab);

    // Output projection with folded Wo + bias
    gemm_3xtf32<<<dim3(Edim / BN, Mrows / BM, 1), 256, SMEM_BYTES>>>(
        ab, wf, wf, wf, out, out, out, bo, Edim, KVdim);
}

// round 9
// speedup vs baseline: 1.2414x; 1.0511x over previous
#include <cuda_runtime.h>
#include <math.h>
#include <stdint.h>

// Problem constants
#define Bdim   2
#define Sdim   2048
#define Edim   2048
#define Hdim   16
#define HKVdim 4
#define Ddim   128
#define KQVdim 2048
#define KVdim  512            // HKV * D — compact Q / attn-out width
#define WIN    256
#define Mrows  (Bdim * Sdim)  // 4096

// Scratch (static __device__ — no allocation allowed)
__device__ float g_q [(size_t)Mrows * KVdim];
__device__ float g_k [(size_t)Mrows * KVdim];
__device__ float g_v [(size_t)Mrows * KVdim];
__device__ float g_ao[(size_t)Mrows * KVdim];
__device__ float g_wf[(size_t)Edim  * KVdim];    // folded Wo

// ---------------------------------------------------------------------------
// 3xTF32 tensor-core GEMM (fp32-accurate): Y = X @ W^T (+bias)
// BM=128, BN=128, BK=16, 256 threads (8 warps 2x4), 64x32 per warp.
// smem holds fp32 (byte-minimal, R4-validated conflict pattern).
// Fragments are double-buffered in registers (software pipeline); the
// hi/lo tf32 split is done in-register: hi = cvt.rna(x), lo = x - hi fed
// RAW to the MMA (hw reads tf32 bits from fp32 layout; truncation of lo
// adds ~2^-24 — negligible).
// ---------------------------------------------------------------------------
#define BM 128
#define BN 128
#define BK 16
#define MSTR (BM + 4)   // 132 floats stride

__device__ __forceinline__ uint32_t f2tf32(float f) {
    uint32_t r;
    asm("cvt.rna.tf32.f32 %0, %1;" : "=r"(r) : "f"(f));
    return r;
}

__device__ __forceinline__ void split2(float f, uint32_t& hi, uint32_t& lo) {
    hi = f2tf32(f);
    lo = __float_as_uint(f - __uint_as_float(hi));   // raw fp32; hw truncates
}

__device__ __forceinline__ void mma_tf32(float c[4], uint32_t a0, uint32_t a1,
                                         uint32_t a2, uint32_t a3,
                                         uint32_t b0, uint32_t b1) {
    asm volatile(
        "mma.sync.aligned.m16n8k8.row.col.f32.tf32.tf32.f32 "
        "{%0,%1,%2,%3}, {%4,%5,%6,%7}, {%8,%9}, {%0,%1,%2,%3};"
        : "+f"(c[0]), "+f"(c[1]), "+f"(c[2]), "+f"(c[3])
        : "r"(a0), "r"(a1), "r"(a2), "r"(a3), "r"(b0), "r"(b1));
}

// Batched: gridDim.z selects (W, Y) pair. K fixed per launch.
__global__ void __launch_bounds__(256)
gemm_3xtf32(const float* __restrict__ X,
            const float* __restrict__ W0, const float* __restrict__ W1,
            const float* __restrict__ W2,
            float* __restrict__ Y0, float* __restrict__ Y1,
            float* __restrict__ Y2,
            const float* __restrict__ bias,
            int N, int K)
{
    __shared__ float As[2][BK][MSTR];
    __shared__ float Bs[2][BK][MSTR];

    const float* W = (blockIdx.z == 0) ? W0 : (blockIdx.z == 1) ? W1 : W2;
    float*       Y = (blockIdx.z == 0) ? Y0 : (blockIdx.z == 1) ? Y1 : Y2;

    const int tid  = threadIdx.x;
    const int warp = tid >> 5;
    const int lane = tid & 31;
    const int g    = lane >> 2;
    const int tg   = lane & 3;
    const int wm   = warp & 1;
    const int wn   = warp >> 1;
    const int bm   = blockIdx.y * BM;
    const int bn   = blockIdx.x * BN;

    const int ldrow0 = tid >> 2;     // rows 0..63 (p=0), +64 (p=1)
    const int ldkv   = tid & 3;

    float acc[4][4][4];
    #pragma unroll
    for (int i = 0; i < 4; i++)
        #pragma unroll
        for (int j = 0; j < 4; j++)
            #pragma unroll
            for (int c = 0; c < 4; c++) acc[i][j][c] = 0.0f;

    // Raw fp32 fragment double-buffers
    float Ar[2][4][4];
    float Br[2][4][2];

    const int T = K / BK;

    // Prologue: tile 0 -> stage 0
    #pragma unroll
    for (int p = 0; p < 2; p++) {
        int row = ldrow0 + p * 64;
        float4 a = *reinterpret_cast<const float4*>(&X[(size_t)(bm + row) * K + ldkv * 4]);
        As[0][ldkv*4+0][row] = a.x; As[0][ldkv*4+1][row] = a.y;
        As[0][ldkv*4+2][row] = a.z; As[0][ldkv*4+3][row] = a.w;
        float4 b = *reinterpret_cast<const float4*>(&W[(size_t)(bn + row) * K + ldkv * 4]);
        Bs[0][ldkv*4+0][row] = b.x; Bs[0][ldkv*4+1][row] = b.y;
        Bs[0][ldkv*4+2][row] = b.z; Bs[0][ldkv*4+3][row] = b.w;
    }
    __syncthreads();

    // Fragment load helper (macro to keep everything in registers)
    #define LOAD_FRAG(buf, st, ks)                                         \
        do {                                                               \
            _Pragma("unroll")                                              \
            for (int i = 0; i < 4; i++) {                                  \
                int row = wm * 64 + i * 16 + g;                            \
                Ar[buf][i][0] = As[st][(ks) + tg    ][row];                \
                Ar[buf][i][1] = As[st][(ks) + tg    ][row + 8];            \
                Ar[buf][i][2] = As[st][(ks) + tg + 4][row];                \
                Ar[buf][i][3] = As[st][(ks) + tg + 4][row + 8];            \
            }                                                              \
            _Pragma("unroll")                                              \
            for (int j = 0; j < 4; j++) {                                  \
                int col = wn * 32 + j * 8 + g;                             \
                Br[buf][j][0] = Bs[st][(ks) + tg    ][col];                \
                Br[buf][j][1] = Bs[st][(ks) + tg + 4][col];                \
            }                                                              \
        } while (0)

    #define MMA_ALL(buf)                                                   \
        do {                                                               \
            uint32_t bh[4][2], bl[4][2];                                   \
            _Pragma("unroll")                                              \
            for (int j = 0; j < 4; j++) {                                  \
                split2(Br[buf][j][0], bh[j][0], bl[j][0]);                 \
                split2(Br[buf][j][1], bh[j][1], bl[j][1]);                 \
            }                                                              \
            _Pragma("unroll")                                              \
            for (int i = 0; i < 4; i++) {                                  \
                uint32_t ah[4], al[4];                                     \
                _Pragma("unroll")                                          \
                for (int c = 0; c < 4; c++)                                \
                    split2(Ar[buf][i][c], ah[c], al[c]);                   \
                _Pragma("unroll")                                          \
                for (int j = 0; j < 4; j++) {                              \
                    mma_tf32(acc[i][j], al[0], al[1], al[2], al[3],        \
                             bh[j][0], bh[j][1]);                         \
                    mma_tf32(acc[i][j], ah[0], ah[1], ah[2], ah[3],        \
                             bl[j][0], bl[j][1]);                         \
                    mma_tf32(acc[i][j], ah[0], ah[1], ah[2], ah[3],        \
                             bh[j][0], bh[j][1]);                         \
                }                                                          \
            }                                                              \
        } while (0)

    LOAD_FRAG(0, 0, 0);

    for (int t = 0; t < T; t++) {
        const int cur = t & 1;
        const int nxt = cur ^ 1;

        // gmem prefetch for next tile (independent LDGs, issued early)
        float4 pa[2], pb[2];
        if (t + 1 < T) {
            const int k0 = (t + 1) * BK;
            #pragma unroll
            for (int p = 0; p < 2; p++) {
                int row = ldrow0 + p * 64;
                pa[p] = *reinterpret_cast<const float4*>(&X[(size_t)(bm + row) * K + k0 + ldkv * 4]);
                pb[p] = *reinterpret_cast<const float4*>(&W[(size_t)(bn + row) * K + k0 + ldkv * 4]);
            }
        }

        // k-half 0: preload ks=8 fragments, then crunch ks=0
        LOAD_FRAG(1, cur, 8);
        MMA_ALL(0);

        // k-half 1: stage next tile, sync, preload next tile's ks=0 frags,
        // then crunch ks=8 (its LDS latency hidden behind these MMAs)
        if (t + 1 < T) {
            #pragma unroll
            for (int p = 0; p < 2; p++) {
                int row = ldrow0 + p * 64;
                As[nxt][ldkv*4+0][row] = pa[p].x; As[nxt][ldkv*4+1][row] = pa[p].y;
                As[nxt][ldkv*4+2][row] = pa[p].z; As[nxt][ldkv*4+3][row] = pa[p].w;
                Bs[nxt][ldkv*4+0][row] = pb[p].x; Bs[nxt][ldkv*4+1][row] = pb[p].y;
                Bs[nxt][ldkv*4+2][row] = pb[p].z; Bs[nxt][ldkv*4+3][row] = pb[p].w;
            }
            __syncthreads();
            LOAD_FRAG(0, nxt, 0);
        }
        MMA_ALL(1);
    }

    #undef LOAD_FRAG
    #undef MMA_ALL

    // Epilogue
    #pragma unroll
    for (int i = 0; i < 4; i++) {
        #pragma unroll
        for (int j = 0; j < 4; j++) {
            int row = bm + wm * 64 + i * 16 + g;
            int col = bn + wn * 32 + j * 8 + 2 * tg;
            float b0 = bias ? bias[col]     : 0.0f;
            float b1 = bias ? bias[col + 1] : 0.0f;
            float2 v0 = make_float2(acc[i][j][0] + b0, acc[i][j][1] + b1);
            float2 v1 = make_float2(acc[i][j][2] + b0, acc[i][j][3] + b1);
            *reinterpret_cast<float2*>(&Y[(size_t)row * N + col])       = v0;
            *reinterpret_cast<float2*>(&Y[(size_t)(row + 8) * N + col]) = v1;
        }
    }
}

// ---------------------------------------------------------------------------
// Fold Wo: Wf[e, g*D+d] = sum_{u=0..3} Wo[e, (4g+u)*D + d]
// ---------------------------------------------------------------------------
__global__ void fold_wo(const float* __restrict__ Wo, float* __restrict__ Wf)
{
    int i = blockIdx.x * blockDim.x + threadIdx.x;
    if (i >= Edim * KVdim) return;
    int e = i / KVdim;
    int c = i % KVdim;
    int gh = c / Ddim, d = c % Ddim;
    float s = 0.0f;
    #pragma unroll
    for (int u = 0; u < 4; u++)
        s += Wo[(size_t)e * KQVdim + (size_t)(gh * 4 + u) * Ddim + d];
    Wf[i] = s;
}

// ---------------------------------------------------------------------------
// Sliding-window GQA attention (flash-style), 4 distinct kv heads.
// ---------------------------------------------------------------------------
__global__ void __launch_bounds__(256, 2)
attn_window(const float* __restrict__ q, const float* __restrict__ k,
            const float* __restrict__ v, float* __restrict__ out)
{
    __shared__ float Qs[32][Ddim];
    __shared__ float Ks[Ddim][33];
    __shared__ float Vs[32][Ddim];

    const int tid  = threadIdx.x;
    const int warp = tid >> 5;
    const int lane = tid & 31;

    const int bh  = blockIdx.y;
    const int b   = bh / HKVdim;
    const int kvh = bh % HKVdim;
    const int q0  = blockIdx.x * 32;

    const float* qptr = q + ((size_t)b * Sdim + q0) * KVdim + kvh * Ddim;

    #pragma unroll
    for (int e = 0; e < 16; e++) {
        int lin = e * 256 + tid;
        int r = lin >> 7, d = lin & 127;
        Qs[r][d] = qptr[(size_t)r * KVdim + d];
    }

    float m[4], l[4], O[4][4];
    #pragma unroll
    for (int r = 0; r < 4; r++) {
        m[r] = -1e30f; l[r] = 0.0f;
        #pragma unroll
        for (int c = 0; c < 4; c++) O[r][c] = 0.0f;
    }

    int ktlo = q0 - (WIN - 1);
    if (ktlo < 0) ktlo = 0;
    ktlo = (ktlo / 32) * 32;

    for (int k0 = ktlo; k0 <= q0; k0 += 32) {
        const float* kptr = k + ((size_t)b * Sdim + k0) * KVdim + kvh * Ddim;
        const float* vptr = v + ((size_t)b * Sdim + k0) * KVdim + kvh * Ddim;
        __syncthreads();
        #pragma unroll
        for (int e = 0; e < 16; e++) {
            int lin = e * 256 + tid;
            int j = lin >> 7, d = lin & 127;
            Ks[d][j] = kptr[(size_t)j * KVdim + d];
            Vs[j][d] = vptr[(size_t)j * KVdim + d];
        }
        __syncthreads();

        #pragma unroll
        for (int r = 0; r < 4; r++) {
            const int row = warp * 4 + r;
            const int i   = q0 + row;
            const int jg  = k0 + lane;

            float s = 0.0f;
            #pragma unroll
            for (int d = 0; d < Ddim; d++)
                s = fmaf(Qs[row][d], Ks[d][lane], s);

            const bool valid = (jg <= i) && (jg > i - WIN);
            s = valid ? s : -1e30f;

            float mt = s;
            #pragma unroll
            for (int off = 16; off; off >>= 1)
                mt = fmaxf(mt, __shfl_xor_sync(0xffffffffu, mt, off));
            const float mnew  = fmaxf(m[r], mt);
            const float p     = valid ? __expf(s - mnew) : 0.0f;
            const float alpha = __expf(m[r] - mnew);
            m[r] = mnew;

            float rs = p;
            #pragma unroll
            for (int off = 16; off; off >>= 1)
                rs += __shfl_xor_sync(0xffffffffu, rs, off);
            l[r] = l[r] * alpha + rs;

            #pragma unroll
            for (int c = 0; c < 4; c++) O[r][c] *= alpha;
            #pragma unroll
            for (int j = 0; j < 32; j++) {
                const float pj = __shfl_sync(0xffffffffu, p, j);
                #pragma unroll
                for (int c = 0; c < 4; c++)
                    O[r][c] = fmaf(pj, Vs[j][c * 32 + lane], O[r][c]);
            }
        }
    }

    float* optr = out + ((size_t)b * Sdim + q0) * KVdim + kvh * Ddim;
    #pragma unroll
    for (int r = 0; r < 4; r++) {
        const int row = warp * 4 + r;
        const float inv = 1.0f / l[r];
        #pragma unroll
        for (int c = 0; c < 4; c++)
            optr[(size_t)row * KVdim + c * 32 + lane] = O[r][c] * inv;
    }
}

// ---------------------------------------------------------------------------
// Launch
// ---------------------------------------------------------------------------
extern "C" void kernel_launch(void* const* d_in, const int* in_sizes, int n_in,
                              void* d_out, int out_size)
{
    const float* x  = (const float*)d_in[0];
    const float* Wq = (const float*)d_in[1];   // only rows 0..511 used
    const float* Wk = (const float*)d_in[2];
    const float* Wv = (const float*)d_in[3];
    const float* Wo = (const float*)d_in[4];
    const float* bo = (const float*)d_in[5];
    float* out = (float*)d_out;

    float *qb, *kb, *vb, *ab, *wf;
    cudaGetSymbolAddress((void**)&qb, g_q);
    cudaGetSymbolAddress((void**)&kb, g_k);
    cudaGetSymbolAddress((void**)&vb, g_v);
    cudaGetSymbolAddress((void**)&ab, g_ao);
    cudaGetSymbolAddress((void**)&wf, g_wf);

    fold_wo<<<(Edim * KVdim + 255) / 256, 256>>>(Wo, wf);

    // Batched QKV projections (z selects weight/output)
    gemm_3xtf32<<<dim3(KVdim / BN, Mrows / BM, 3), 256>>>(
        x, Wq, Wk, Wv, qb, kb, vb, nullptr, KVdim, Edim);

    attn_window<<<dim3(Sdim / 32, Bdim * HKVdim), 256>>>(qb, kb, vb, ab);

    // Output projection with folded Wo + bias
    gemm_3xtf32<<<dim3(Edim / BN, Mrows / BM, 1), 256>>>(
        ab, wf, wf, wf, out, out, out, bo, Edim, KVdim);
}

// round 10
// speedup vs baseline: 1.3120x; 1.0569x over previous
#include <cuda_runtime.h>
#include <math.h>
#include <stdint.h>

// Problem constants
#define Bdim   2
#define Sdim   2048
#define Edim   2048
#define Hdim   16
#define HKVdim 4
#define Ddim   128
#define KQVdim 2048
#define KVdim  512            // HKV * D — compact Q / attn-out width
#define WIN    256
#define Mrows  (Bdim * Sdim)  // 4096

// Scratch (static __device__ — no allocation allowed)
__device__ float g_q [(size_t)Mrows * KVdim];
__device__ float g_k [(size_t)Mrows * KVdim];
__device__ float g_v [(size_t)Mrows * KVdim];
__device__ float g_ao[(size_t)Mrows * KVdim];
__device__ float g_wf[(size_t)Edim  * KVdim];    // folded Wo

// ---------------------------------------------------------------------------
// 3xTF32 tensor-core GEMM (fp32-accurate): Y = X @ W^T (+bias)
// BM=128, BN=64, BK=16, 256 threads (8 warps: 4 along M x 2 along N),
// 32x32 per warp. 2 CTAs/SM via __launch_bounds__(256,2) — the R8 profile
// showed latency starvation (occ 12.4%, issue 39%, tensor 47%); this trades
// a slightly fatter issue stream for 2x warps/SMSP.
// smem fp32 (byte-minimal); in-register hi/lo split; fragment double-buffer.
// ---------------------------------------------------------------------------
#define BM 128
#define BN 64
#define BK 16
#define MSTR (BM + 4)   // 132
#define NSTR (BN + 4)   // 68

__device__ __forceinline__ uint32_t f2tf32(float f) {
    uint32_t r;
    asm("cvt.rna.tf32.f32 %0, %1;" : "=r"(r) : "f"(f));
    return r;
}

__device__ __forceinline__ void split2(float f, uint32_t& hi, uint32_t& lo) {
    hi = f2tf32(f);
    lo = __float_as_uint(f - __uint_as_float(hi));   // raw fp32; hw truncates
}

__device__ __forceinline__ void mma_tf32(float c[4], uint32_t a0, uint32_t a1,
                                         uint32_t a2, uint32_t a3,
                                         uint32_t b0, uint32_t b1) {
    asm volatile(
        "mma.sync.aligned.m16n8k8.row.col.f32.tf32.tf32.f32 "
        "{%0,%1,%2,%3}, {%4,%5,%6,%7}, {%8,%9}, {%0,%1,%2,%3};"
        : "+f"(c[0]), "+f"(c[1]), "+f"(c[2]), "+f"(c[3])
        : "r"(a0), "r"(a1), "r"(a2), "r"(a3), "r"(b0), "r"(b1));
}

// Batched: gridDim.z selects (W, Y) pair. K fixed per launch.
__global__ void __launch_bounds__(256, 2)
gemm_3xtf32(const float* __restrict__ X,
            const float* __restrict__ W0, const float* __restrict__ W1,
            const float* __restrict__ W2,
            float* __restrict__ Y0, float* __restrict__ Y1,
            float* __restrict__ Y2,
            const float* __restrict__ bias,
            int N, int K)
{
    __shared__ float As[2][BK][MSTR];
    __shared__ float Bs[2][BK][NSTR];

    const float* W = (blockIdx.z == 0) ? W0 : (blockIdx.z == 1) ? W1 : W2;
    float*       Y = (blockIdx.z == 0) ? Y0 : (blockIdx.z == 1) ? Y1 : Y2;

    const int tid  = threadIdx.x;
    const int warp = tid >> 5;
    const int lane = tid & 31;
    const int g    = lane >> 2;        // 0..7
    const int tg   = lane & 3;         // 0..3
    const int wm   = warp & 3;         // 0..3: 32 M-rows each
    const int wn   = warp >> 2;        // 0..1: 32 N-cols each
    const int bm   = blockIdx.y * BM;
    const int bn   = blockIdx.x * BN;

    const int ldrow = tid >> 2;        // 0..63
    const int ldkv  = tid & 3;

    float acc[2][4][4];
    #pragma unroll
    for (int i = 0; i < 2; i++)
        #pragma unroll
        for (int j = 0; j < 4; j++)
            #pragma unroll
            for (int c = 0; c < 4; c++) acc[i][j][c] = 0.0f;

    // Raw fp32 fragment double-buffers
    float Ar[2][2][4];
    float Br[2][4][2];

    const int T = K / BK;

    // Prologue: tile 0 -> stage 0
    #pragma unroll
    for (int p = 0; p < 2; p++) {
        int row = ldrow + p * 64;
        float4 a = *reinterpret_cast<const float4*>(&X[(size_t)(bm + row) * K + ldkv * 4]);
        As[0][ldkv*4+0][row] = a.x; As[0][ldkv*4+1][row] = a.y;
        As[0][ldkv*4+2][row] = a.z; As[0][ldkv*4+3][row] = a.w;
    }
    {
        float4 b = *reinterpret_cast<const float4*>(&W[(size_t)(bn + ldrow) * K + ldkv * 4]);
        Bs[0][ldkv*4+0][ldrow] = b.x; Bs[0][ldkv*4+1][ldrow] = b.y;
        Bs[0][ldkv*4+2][ldrow] = b.z; Bs[0][ldkv*4+3][ldrow] = b.w;
    }
    __syncthreads();

    #define LOAD_FRAG(buf, st, ks)                                         \
        do {                                                               \
            _Pragma("unroll")                                              \
            for (int i = 0; i < 2; i++) {                                  \
                int row = wm * 32 + i * 16 + g;                            \
                Ar[buf][i][0] = As[st][(ks) + tg    ][row];                \
                Ar[buf][i][1] = As[st][(ks) + tg    ][row + 8];            \
                Ar[buf][i][2] = As[st][(ks) + tg + 4][row];                \
                Ar[buf][i][3] = As[st][(ks) + tg + 4][row + 8];            \
            }                                                              \
            _Pragma("unroll")                                              \
            for (int j = 0; j < 4; j++) {                                  \
                int col = wn * 32 + j * 8 + g;                             \
                Br[buf][j][0] = Bs[st][(ks) + tg    ][col];                \
                Br[buf][j][1] = Bs[st][(ks) + tg + 4][col];                \
            }                                                              \
        } while (0)

    #define MMA_ALL(buf)                                                   \
        do {                                                               \
            uint32_t bh[4][2], bl[4][2];                                   \
            _Pragma("unroll")                                              \
            for (int j = 0; j < 4; j++) {                                  \
                split2(Br[buf][j][0], bh[j][0], bl[j][0]);                 \
                split2(Br[buf][j][1], bh[j][1], bl[j][1]);                 \
            }                                                              \
            _Pragma("unroll")                                              \
            for (int i = 0; i < 2; i++) {                                  \
                uint32_t ah[4], al[4];                                     \
                _Pragma("unroll")                                          \
                for (int c = 0; c < 4; c++)                                \
                    split2(Ar[buf][i][c], ah[c], al[c]);                   \
                _Pragma("unroll")                                          \
                for (int j = 0; j < 4; j++) {                              \
                    mma_tf32(acc[i][j], al[0], al[1], al[2], al[3],        \
                             bh[j][0], bh[j][1]);                         \
                    mma_tf32(acc[i][j], ah[0], ah[1], ah[2], ah[3],        \
                             bl[j][0], bl[j][1]);                         \
                    mma_tf32(acc[i][j], ah[0], ah[1], ah[2], ah[3],        \
                             bh[j][0], bh[j][1]);                         \
                }                                                          \
            }                                                              \
        } while (0)

    LOAD_FRAG(0, 0, 0);

    for (int t = 0; t < T; t++) {
        const int cur = t & 1;
        const int nxt = cur ^ 1;

        // gmem prefetch for next tile (independent LDGs, issued early)
        float4 pa[2], pb;
        if (t + 1 < T) {
            const int k0 = (t + 1) * BK;
            #pragma unroll
            for (int p = 0; p < 2; p++) {
                int row = ldrow + p * 64;
                pa[p] = *reinterpret_cast<const float4*>(&X[(size_t)(bm + row) * K + k0 + ldkv * 4]);
            }
            pb = *reinterpret_cast<const float4*>(&W[(size_t)(bn + ldrow) * K + k0 + ldkv * 4]);
        }

        // k-half 0: preload ks=8 fragments, then crunch ks=0
        LOAD_FRAG(1, cur, 8);
        MMA_ALL(0);

        // k-half 1: stage next tile, sync, preload next ks=0 frags, crunch ks=8
        if (t + 1 < T) {
            #pragma unroll
            for (int p = 0; p < 2; p++) {
                int row = ldrow + p * 64;
                As[nxt][ldkv*4+0][row] = pa[p].x; As[nxt][ldkv*4+1][row] = pa[p].y;
                As[nxt][ldkv*4+2][row] = pa[p].z; As[nxt][ldkv*4+3][row] = pa[p].w;
            }
            Bs[nxt][ldkv*4+0][ldrow] = pb.x; Bs[nxt][ldkv*4+1][ldrow] = pb.y;
            Bs[nxt][ldkv*4+2][ldrow] = pb.z; Bs[nxt][ldkv*4+3][ldrow] = pb.w;
            __syncthreads();
            LOAD_FRAG(0, nxt, 0);
        }
        MMA_ALL(1);
    }

    #undef LOAD_FRAG
    #undef MMA_ALL

    // Epilogue
    #pragma unroll
    for (int i = 0; i < 2; i++) {
        #pragma unroll
        for (int j = 0; j < 4; j++) {
            int row = bm + wm * 32 + i * 16 + g;
            int col = bn + wn * 32 + j * 8 + 2 * tg;
            float b0 = bias ? bias[col]     : 0.0f;
            float b1 = bias ? bias[col + 1] : 0.0f;
            float2 v0 = make_float2(acc[i][j][0] + b0, acc[i][j][1] + b1);
            float2 v1 = make_float2(acc[i][j][2] + b0, acc[i][j][3] + b1);
            *reinterpret_cast<float2*>(&Y[(size_t)row * N + col])       = v0;
            *reinterpret_cast<float2*>(&Y[(size_t)(row + 8) * N + col]) = v1;
        }
    }
}

// ---------------------------------------------------------------------------
// Fold Wo: Wf[e, g*D+d] = sum_{u=0..3} Wo[e, (4g+u)*D + d]
// ---------------------------------------------------------------------------
__global__ void fold_wo(const float* __restrict__ Wo, float* __restrict__ Wf)
{
    int i = blockIdx.x * blockDim.x + threadIdx.x;
    if (i >= Edim * KVdim) return;
    int e = i / KVdim;
    int c = i % KVdim;
    int gh = c / Ddim, d = c % Ddim;
    float s = 0.0f;
    #pragma unroll
    for (int u = 0; u < 4; u++)
        s += Wo[(size_t)e * KQVdim + (size_t)(gh * 4 + u) * Ddim + d];
    Wf[i] = s;
}

// ---------------------------------------------------------------------------
// Sliding-window GQA attention (flash-style), 4 distinct kv heads.
// ---------------------------------------------------------------------------
__global__ void __launch_bounds__(256, 2)
attn_window(const float* __restrict__ q, const float* __restrict__ k,
            const float* __restrict__ v, float* __restrict__ out)
{
    __shared__ float Qs[32][Ddim];
    __shared__ float Ks[Ddim][33];
    __shared__ float Vs[32][Ddim];

    const int tid  = threadIdx.x;
    const int warp = tid >> 5;
    const int lane = tid & 31;

    const int bh  = blockIdx.y;
    const int b   = bh / HKVdim;
    const int kvh = bh % HKVdim;
    const int q0  = blockIdx.x * 32;

    const float* qptr = q + ((size_t)b * Sdim + q0) * KVdim + kvh * Ddim;

    #pragma unroll
    for (int e = 0; e < 16; e++) {
        int lin = e * 256 + tid;
        int r = lin >> 7, d = lin & 127;
        Qs[r][d] = qptr[(size_t)r * KVdim + d];
    }

    float m[4], l[4], O[4][4];
    #pragma unroll
    for (int r = 0; r < 4; r++) {
        m[r] = -1e30f; l[r] = 0.0f;
        #pragma unroll
        for (int c = 0; c < 4; c++) O[r][c] = 0.0f;
    }

    int ktlo = q0 - (WIN - 1);
    if (ktlo < 0) ktlo = 0;
    ktlo = (ktlo / 32) * 32;

    for (int k0 = ktlo; k0 <= q0; k0 += 32) {
        const float* kptr = k + ((size_t)b * Sdim + k0) * KVdim + kvh * Ddim;
        const float* vptr = v + ((size_t)b * Sdim + k0) * KVdim + kvh * Ddim;
        __syncthreads();
        #pragma unroll
        for (int e = 0; e < 16; e++) {
            int lin = e * 256 + tid;
            int j = lin >> 7, d = lin & 127;
            Ks[d][j] = kptr[(size_t)j * KVdim + d];
            Vs[j][d] = vptr[(size_t)j * KVdim + d];
        }
        __syncthreads();

        #pragma unroll
        for (int r = 0; r < 4; r++) {
            const int row = warp * 4 + r;
            const int i   = q0 + row;
            const int jg  = k0 + lane;

            float s = 0.0f;
            #pragma unroll
            for (int d = 0; d < Ddim; d++)
                s = fmaf(Qs[row][d], Ks[d][lane], s);

            const bool valid = (jg <= i) && (jg > i - WIN);
            s = valid ? s : -1e30f;

            float mt = s;
            #pragma unroll
            for (int off = 16; off; off >>= 1)
                mt = fmaxf(mt, __shfl_xor_sync(0xffffffffu, mt, off));
            const float mnew  = fmaxf(m[r], mt);
            const float p     = valid ? __expf(s - mnew) : 0.0f;
            const float alpha = __expf(m[r] - mnew);
            m[r] = mnew;

            float rs = p;
            #pragma unroll
            for (int off = 16; off; off >>= 1)
                rs += __shfl_xor_sync(0xffffffffu, rs, off);
            l[r] = l[r] * alpha + rs;

            #pragma unroll
            for (int c = 0; c < 4; c++) O[r][c] *= alpha;
            #pragma unroll
            for (int j = 0; j < 32; j++) {
                const float pj = __shfl_sync(0xffffffffu, p, j);
                #pragma unroll
                for (int c = 0; c < 4; c++)
                    O[r][c] = fmaf(pj, Vs[j][c * 32 + lane], O[r][c]);
            }
        }
    }

    float* optr = out + ((size_t)b * Sdim + q0) * KVdim + kvh * Ddim;
    #pragma unroll
    for (int r = 0; r < 4; r++) {
        const int row = warp * 4 + r;
        const float inv = 1.0f / l[r];
        #pragma unroll
        for (int c = 0; c < 4; c++)
            optr[(size_t)row * KVdim + c * 32 + lane] = O[r][c] * inv;
    }
}

// ---------------------------------------------------------------------------
// Launch
// ---------------------------------------------------------------------------
extern "C" void kernel_launch(void* const* d_in, const int* in_sizes, int n_in,
                              void* d_out, int out_size)
{
    const float* x  = (const float*)d_in[0];
    const float* Wq = (const float*)d_in[1];   // only rows 0..511 used
    const float* Wk = (const float*)d_in[2];
    const float* Wv = (const float*)d_in[3];
    const float* Wo = (const float*)d_in[4];
    const float* bo = (const float*)d_in[5];
    float* out = (float*)d_out;

    float *qb, *kb, *vb, *ab, *wf;
    cudaGetSymbolAddress((void**)&qb, g_q);
    cudaGetSymbolAddress((void**)&kb, g_k);
    cudaGetSymbolAddress((void**)&vb, g_v);
    cudaGetSymbolAddress((void**)&ab, g_ao);
    cudaGetSymbolAddress((void**)&wf, g_wf);

    fold_wo<<<(Edim * KVdim + 255) / 256, 256>>>(Wo, wf);

    // Batched QKV projections (z selects weight/output)
    gemm_3xtf32<<<dim3(KVdim / BN, Mrows / BM, 3), 256>>>(
        x, Wq, Wk, Wv, qb, kb, vb, nullptr, KVdim, Edim);

    attn_window<<<dim3(Sdim / 32, Bdim * HKVdim), 256>>>(qb, kb, vb, ab);

    // Output projection with folded Wo + bias
    gemm_3xtf32<<<dim3(Edim / BN, Mrows / BM, 1), 256>>>(
        ab, wf, wf, wf, out, out, out, bo, Edim, KVdim);
}